// round 1
// baseline (speedup 1.0000x reference)
#include <cuda_runtime.h>
#include <math.h>

// ---------------------------------------------------------------------------
// PairContrastiveLoss: patch-embed (conv s=16) -> softmax/log_softmax ->
// CE[i,j] = -(1/196) * sum_{p,c} logp[i,p,c] * q[j,p,c]
// Using sum_c q = 1:  CE[i,j] = (L[i] - S[i,j]) / 196,
//   S = Xp_raw @ Q^T,  L[i] = sum_p lse(xp[i,p,:])
// out = (trace(CE)/B) / ((sum(CE)-trace(CE))/(B^2-B))
// ---------------------------------------------------------------------------

#define BSZ   64
#define CC    3
#define IMG   224
#define PT    16
#define HP    14
#define NP    196          // patches per image
#define HID   384
#define KDIM  768          // C*16*16
#define MROWS 12544        // BSZ*NP
#define KTOT  75264        // NP*HID

// scratch (static device memory; no allocations allowed)
__device__ float g_Wt[KDIM * HID];        // W transposed: [k][o]
__device__ float g_embx[(size_t)MROWS * HID];
__device__ float g_emby[(size_t)MROWS * HID];
__device__ float g_lse[MROWS];
__device__ float g_L[BSZ];
__device__ float g_S[BSZ * BSZ];

// ---------------------------------------------------------------- transpose W
__global__ void k_transpose(const float* __restrict__ Wc) {
    int idx = blockIdx.x * 256 + threadIdx.x;
    if (idx < KDIM * HID) {
        int o = idx / KDIM;
        int k = idx - o * KDIM;
        g_Wt[k * HID + o] = Wc[idx];
    }
}

// ------------------------------------------------- patch-embed implicit GEMM
// M=12544 (per image), N=384, K=768.  BM=BN=64, BK=16, 4x4 microtile.
__global__ __launch_bounds__(256) void k_patch_gemm(
        const float* __restrict__ x, const float* __restrict__ y,
        const float* __restrict__ bias) {
    const float* img = blockIdx.z ? y : x;
    float* emb = blockIdx.z ? g_emby : g_embx;

    __shared__ float As[16][65];   // [k][m], padded
    __shared__ float Bs[16][64];   // [k][n]

    const int tid = threadIdx.x;
    const int tx = tid & 15, ty = tid >> 4;
    const int m0 = blockIdx.y * 64;
    const int n0 = blockIdx.x * 64;

    // A-load geometry: this thread loads 4 consecutive k for one m
    const int mlocal = tid >> 2;           // 0..63
    const int klo    = (tid & 3) * 4;      // 0,4,8,12
    const int m  = m0 + mlocal;
    const int b  = m / NP;
    const int p  = m - b * NP;
    const int ph = p / HP;
    const int pw = p - ph * HP;
    const int abase = (b * CC) * (IMG * IMG) + (ph * PT) * IMG + pw * PT;

    float acc[4][4] = {};

    for (int k0 = 0; k0 < KDIM; k0 += 16) {
        // for this k-tile: channel + row are constant, col = k_local
        const int c = k0 >> 8;
        const int r = (k0 >> 4) & 15;
        float4 av = *(const float4*)(img + abase + c * (IMG * IMG) + r * IMG + klo);
        float4 bv = *(const float4*)(g_Wt + (size_t)(k0 + ty) * HID + n0 + tx * 4);

        __syncthreads();
        As[klo + 0][mlocal] = av.x;
        As[klo + 1][mlocal] = av.y;
        As[klo + 2][mlocal] = av.z;
        As[klo + 3][mlocal] = av.w;
        *(float4*)&Bs[ty][tx * 4] = bv;
        __syncthreads();

        #pragma unroll
        for (int kk = 0; kk < 16; ++kk) {
            float a0 = As[kk][ty * 4 + 0];
            float a1 = As[kk][ty * 4 + 1];
            float a2 = As[kk][ty * 4 + 2];
            float a3 = As[kk][ty * 4 + 3];
            float4 b4 = *(const float4*)&Bs[kk][tx * 4];
            acc[0][0] += a0 * b4.x; acc[0][1] += a0 * b4.y; acc[0][2] += a0 * b4.z; acc[0][3] += a0 * b4.w;
            acc[1][0] += a1 * b4.x; acc[1][1] += a1 * b4.y; acc[1][2] += a1 * b4.z; acc[1][3] += a1 * b4.w;
            acc[2][0] += a2 * b4.x; acc[2][1] += a2 * b4.y; acc[2][2] += a2 * b4.z; acc[2][3] += a2 * b4.w;
            acc[3][0] += a3 * b4.x; acc[3][1] += a3 * b4.y; acc[3][2] += a3 * b4.z; acc[3][3] += a3 * b4.w;
        }
    }

    float4 bb = *(const float4*)(bias + n0 + tx * 4);
    #pragma unroll
    for (int i = 0; i < 4; ++i) {
        float4 o;
        o.x = acc[i][0] + bb.x;
        o.y = acc[i][1] + bb.y;
        o.z = acc[i][2] + bb.z;
        o.w = acc[i][3] + bb.w;
        *(float4*)(emb + (size_t)(m0 + ty * 4 + i) * HID + n0 + tx * 4) = o;
    }
}

// ---------------------------------------------------------- row softmax (y)
__global__ void k_softmax_y() {
    const int row = blockIdx.x;
    float* v = g_emby + (size_t)row * HID;
    const int tid = threadIdx.x;                 // 128 threads, 3 elems each
    float a0 = v[tid], a1 = v[tid + 128], a2 = v[tid + 256];

    __shared__ float red[4];
    float mx = fmaxf(a0, fmaxf(a1, a2));
    #pragma unroll
    for (int o = 16; o; o >>= 1) mx = fmaxf(mx, __shfl_xor_sync(0xffffffffu, mx, o));
    if ((tid & 31) == 0) red[tid >> 5] = mx;
    __syncthreads();
    mx = fmaxf(fmaxf(red[0], red[1]), fmaxf(red[2], red[3]));

    float e0 = __expf(a0 - mx), e1 = __expf(a1 - mx), e2 = __expf(a2 - mx);
    float s = e0 + e1 + e2;
    #pragma unroll
    for (int o = 16; o; o >>= 1) s += __shfl_xor_sync(0xffffffffu, s, o);
    __shared__ float red2[4];
    if ((tid & 31) == 0) red2[tid >> 5] = s;
    __syncthreads();
    s = red2[0] + red2[1] + red2[2] + red2[3];

    float inv = 1.0f / s;
    v[tid] = e0 * inv; v[tid + 128] = e1 * inv; v[tid + 256] = e2 * inv;
}

// -------------------------------------------------------------- row lse (x)
__global__ void k_lse_x() {
    const int row = blockIdx.x;
    const float* v = g_embx + (size_t)row * HID;
    const int tid = threadIdx.x;
    float a0 = v[tid], a1 = v[tid + 128], a2 = v[tid + 256];

    __shared__ float red[4];
    float mx = fmaxf(a0, fmaxf(a1, a2));
    #pragma unroll
    for (int o = 16; o; o >>= 1) mx = fmaxf(mx, __shfl_xor_sync(0xffffffffu, mx, o));
    if ((tid & 31) == 0) red[tid >> 5] = mx;
    __syncthreads();
    mx = fmaxf(fmaxf(red[0], red[1]), fmaxf(red[2], red[3]));

    float s = __expf(a0 - mx) + __expf(a1 - mx) + __expf(a2 - mx);
    #pragma unroll
    for (int o = 16; o; o >>= 1) s += __shfl_xor_sync(0xffffffffu, s, o);
    __shared__ float red2[4];
    if ((tid & 31) == 0) red2[tid >> 5] = s;
    __syncthreads();
    if (tid == 0) {
        s = red2[0] + red2[1] + red2[2] + red2[3];
        g_lse[row] = mx + __logf(s);
    }
}

// ----------------------------------------------------- L[b] = sum_p lse[b,p]
__global__ void k_reduceL() {
    const int b = blockIdx.x;
    const int tid = threadIdx.x;                 // 256 threads
    float v = (tid < NP) ? g_lse[b * NP + tid] : 0.0f;
    #pragma unroll
    for (int o = 16; o; o >>= 1) v += __shfl_xor_sync(0xffffffffu, v, o);
    __shared__ float red[8];
    if ((tid & 31) == 0) red[tid >> 5] = v;
    __syncthreads();
    if (tid == 0) {
        float s = 0.0f;
        #pragma unroll
        for (int w = 0; w < 8; ++w) s += red[w];
        g_L[b] = s;
    }
}

// -------------------------------- S = Xp_raw @ Q^T  (64x64, K=75264)
#define KC 512
__global__ __launch_bounds__(256) void k_sgemm() {
    __shared__ float Xs[8 * 513];
    __shared__ float Qs[8 * 513];
    const int tid = threadIdx.x;
    const int gi0 = blockIdx.y * 8, gj0 = blockIdx.x * 8;
    const int pair = tid & 63, part = tid >> 6;
    const int i = pair >> 3, j = pair & 7;

    float acc = 0.0f;
    for (int k0 = 0; k0 < KTOT; k0 += KC) {
        __syncthreads();
        #pragma unroll
        for (int li = tid; li < 8 * KC; li += 256) {
            int row = li >> 9, kk = li & (KC - 1);
            Xs[row * 513 + kk] = g_embx[(size_t)(gi0 + row) * KTOT + k0 + kk];
            Qs[row * 513 + kk] = g_emby[(size_t)(gj0 + row) * KTOT + k0 + kk];
        }
        __syncthreads();
        const int kb = part * 128;
        const float* xr = &Xs[i * 513 + kb];
        const float* qr = &Qs[j * 513 + kb];
        #pragma unroll 8
        for (int kk = 0; kk < 128; ++kk) acc += xr[kk] * qr[kk];
    }

    __shared__ float red[256];
    red[part * 64 + pair] = acc;
    __syncthreads();
    if (tid < 64) {
        float s = red[tid] + red[64 + tid] + red[128 + tid] + red[192 + tid];
        int ii = tid >> 3, jj = tid & 7;
        g_S[(gi0 + ii) * 64 + (gj0 + jj)] = s;
    }
}

// ------------------------------------------------------------- final scalar
__global__ void k_final(float* __restrict__ out) {
    const int tid = threadIdx.x;                 // 256 threads
    float tot = 0.0f, diag = 0.0f;
    for (int idx = tid; idx < 4096; idx += 256) {
        int i = idx >> 6, j = idx & 63;
        float ce = (g_L[i] - g_S[idx]) * (1.0f / 196.0f);
        tot += ce;
        if (i == j) diag += ce;
    }
    #pragma unroll
    for (int o = 16; o; o >>= 1) {
        tot  += __shfl_xor_sync(0xffffffffu, tot,  o);
        diag += __shfl_xor_sync(0xffffffffu, diag, o);
    }
    __shared__ float rt[8], rd[8];
    if ((tid & 31) == 0) { rt[tid >> 5] = tot; rd[tid >> 5] = diag; }
    __syncthreads();
    if (tid == 0) {
        float T = 0.0f, D = 0.0f;
        #pragma unroll
        for (int w = 0; w < 8; ++w) { T += rt[w]; D += rd[w]; }
        float close = D / 64.0f;
        float far   = (T - D) / (4096.0f - 64.0f);
        out[0] = close / far;
    }
}

// ---------------------------------------------------------------------------
extern "C" void kernel_launch(void* const* d_in, const int* in_sizes, int n_in,
                              void* d_out, int out_size) {
    const float* x  = (const float*)d_in[0];
    const float* y  = (const float*)d_in[1];
    const float* Wc = (const float*)d_in[2];
    const float* b  = (const float*)d_in[3];
    float* out = (float*)d_out;

    k_transpose<<<(KDIM * HID + 255) / 256, 256>>>(Wc);

    dim3 g2(HID / 64, MROWS / 64, 2);            // (6, 196, 2)
    k_patch_gemm<<<g2, 256>>>(x, y, b);

    k_softmax_y<<<MROWS, 128>>>();
    k_lse_x<<<MROWS, 128>>>();
    k_reduceL<<<BSZ, 256>>>();

    dim3 g4(8, 8);
    k_sgemm<<<g4, 256>>>();

    k_final<<<1, 256>>>(out);
}

// round 6
// speedup vs baseline: 3.8746x; 3.8746x over previous
#include <cuda_runtime.h>
#include <cuda_bf16.h>
#include <math.h>
#include <stdint.h>

// ---------------------------------------------------------------------------
// PairContrastiveLoss via mma.sync (HMMA bf16) — tcgen05 unavailable at the
// harness's compute_103 PTX target.
//   emb = im2col(x|y) @ W^T + b   (bf16 inputs, fp32 accum, fused im2col)
//   CE[i,j] = (L[i] - S[i,j]) / 196,  S = Xp_raw @ q^T, L[i] = sum_p lse
//   out = (trace/B) / ((sum-trace)/(B^2-B))
// ---------------------------------------------------------------------------

#define BSZ   64
#define NP    196
#define HID   384
#define KDIM  768
#define MROWS 12544
#define KTOT  75264
#define NKB   588         // k-split blocks for S gemm (KTOT/128)

__device__ __nv_bfloat16 g_Wt[KDIM * HID];                  // [k][n] bf16
__device__ float g_embx[(size_t)MROWS * HID];               // raw x logits
__device__ float g_emby[(size_t)MROWS * HID];               // y logits -> q
__device__ float g_lse[MROWS];
__device__ float g_L[BSZ];
__device__ float g_Spart[NKB * 4096];
__device__ float g_S[4096];

// ------------------------------------------------------------- PTX helpers
__device__ __forceinline__ uint32_t smem_u32(const void* p) {
    uint32_t a;
    asm("{ .reg .u64 t; cvta.to.shared.u64 t, %1; cvt.u32.u64 %0, t; }"
        : "=r"(a) : "l"(p));
    return a;
}
__device__ __forceinline__ void cp_async16(uint32_t dst, const void* src) {
    asm volatile("cp.async.cg.shared.global [%0], [%1], 16;" :: "r"(dst), "l"(src));
}
#define CP_COMMIT() asm volatile("cp.async.commit_group;" ::: "memory")
#define CP_WAIT(n)  asm volatile("cp.async.wait_group %0;" :: "n"(n) : "memory")

__device__ __forceinline__ void ldm_x4(uint32_t* r, uint32_t addr) {
    asm volatile("ldmatrix.sync.aligned.m8n8.x4.shared.b16 {%0,%1,%2,%3}, [%4];"
        : "=r"(r[0]), "=r"(r[1]), "=r"(r[2]), "=r"(r[3]) : "r"(addr));
}
__device__ __forceinline__ void ldm_x4t(uint32_t* r, uint32_t addr) {
    asm volatile("ldmatrix.sync.aligned.m8n8.x4.trans.shared.b16 {%0,%1,%2,%3}, [%4];"
        : "=r"(r[0]), "=r"(r[1]), "=r"(r[2]), "=r"(r[3]) : "r"(addr));
}
__device__ __forceinline__ void mma16816(float* d, const uint32_t* a,
                                         uint32_t b0, uint32_t b1) {
    asm volatile(
        "mma.sync.aligned.m16n8k16.row.col.f32.bf16.bf16.f32 "
        "{%0,%1,%2,%3}, {%4,%5,%6,%7}, {%8,%9}, {%0,%1,%2,%3};"
        : "+f"(d[0]), "+f"(d[1]), "+f"(d[2]), "+f"(d[3])
        : "r"(a[0]), "r"(a[1]), "r"(a[2]), "r"(a[3]), "r"(b0), "r"(b1));
}

// ------------------------------------------------------------------ prep W
// Wc: [384][768] row-major -> g_Wt: [k=768][n=384] bf16
__global__ void k_prep_w(const float* __restrict__ Wc) {
    int idx = blockIdx.x * 256 + threadIdx.x;
    if (idx < KDIM * HID) {
        int k = idx / HID, n = idx - k * HID;
        g_Wt[idx] = __float2bfloat16_rn(Wc[n * KDIM + k]);
    }
}

// ------------------------------------------------ HMMA patch-embed GEMM
// CTA: BM=64 rows x BN=384 (full N), BK=32, 24 k-iters, 8 warps (2m x 4n).
// A: fused im2col, fp32 LDG -> bf16 STS (reg-prefetched one stage ahead).
// B: cp.async bf16 from g_Wt, double-buffered.
#define APAD   40                       // 32 + 8 pad (bf16 elems)
#define BPAD   392                      // 384 + 8 pad
#define A_ST   (64 * APAD * 2)          // 5120 B per stage
#define B_ST   (32 * BPAD * 2)          // 25088 B per stage
#define SM_A0  0
#define SM_A1  A_ST
#define SM_B0  (2 * A_ST)
#define SM_B1  (2 * A_ST + B_ST)
#define SM_GEMM (2 * A_ST + 2 * B_ST)   // 60416 B

__global__ void __launch_bounds__(256) k_gemm(
        const float* __restrict__ x, const float* __restrict__ y,
        const float* __restrict__ bias) {
    extern __shared__ char smem[];
    const uint32_t sb = smem_u32(smem);
    const int tid = threadIdx.x;
    const int lane = tid & 31;
    const int wid = tid >> 5;
    const int wm = wid >> 2;            // 0..1
    const int wn = wid & 3;             // 0..3
    const int m0 = blockIdx.x * 64;
    const int img = blockIdx.y;
    const float* im = img ? y : x;

    // ---- A-load geometry (fixed per thread): rows r_a, r_a+32; seg s_a
    const int r_a = tid >> 3;           // 0..31
    const int s_a = tid & 7;            // 8 float4 segs per row
    const int srr  = s_a >> 2;          // 0/1 : second image row of chunk
    const int col4 = (s_a & 3) * 4;
    int base_r[2];
    #pragma unroll
    for (int h = 0; h < 2; ++h) {
        int m = m0 + r_a + h * 32;
        int b = m / NP, p = m - b * NP;
        int ph = p / 14, pw = p - ph * 14;
        base_r[h] = (b * 3 * 224 + ph * 16) * 224 + pw * 16 + col4;
    }
    const uint32_t a_dst_e = r_a * APAD + srr * 16 + (s_a & 3) * 4;  // elem idx

    const uint32_t Aoff[2] = {SM_A0, SM_A1};
    const uint32_t Boff[2] = {SM_B0, SM_B1};

    // ---- B cp.async geometry: 6 x 16B per thread per stage
    // idx = tid + it*256 : row = idx/48 (0..31), seg = idx%48

    float acc[2][12][4] = {};

    // helpers ------------------------------------------------------------
    auto issueB = [&](int j, int buf) {
        #pragma unroll
        for (int it = 0; it < 6; ++it) {
            int idx = tid + it * 256;
            int row = idx / 48, seg = idx - row * 48;
            cp_async16(sb + Boff[buf] + row * (BPAD * 2) + seg * 16,
                       g_Wt + (size_t)(j * 32 + row) * HID + seg * 8);
        }
        CP_COMMIT();
    };
    auto ldgA = [&](int j, float4* av) {
        const int c = j >> 3, r0 = (j & 7) * 2;
        const int off = c * 50176 + (r0 + srr) * 224;
        av[0] = *(const float4*)(im + base_r[0] + off);
        av[1] = *(const float4*)(im + base_r[1] + off);
    };
    auto stsA = [&](int buf, const float4* av) {
        #pragma unroll
        for (int h = 0; h < 2; ++h) {
            __nv_bfloat162 p0 = __floats2bfloat162_rn(av[h].x, av[h].y);
            __nv_bfloat162 p1 = __floats2bfloat162_rn(av[h].z, av[h].w);
            char* d = smem + Aoff[buf] + (a_dst_e + h * 32 * APAD) * 2;
            *(uint32_t*)d       = *(uint32_t*)&p0;
            *(uint32_t*)(d + 4) = *(uint32_t*)&p1;
        }
    };

    // ---- prologue: stage 0
    {
        float4 av[2];
        ldgA(0, av);
        stsA(0, av);
        issueB(0, 0);
    }

    float4 nxt[2];
    for (int j = 0; j < 24; ++j) {
        const int buf = j & 1;
        if (j < 23) {
            ldgA(j + 1, nxt);           // LDG early: latency hidden by compute
            issueB(j + 1, buf ^ 1);
            CP_WAIT(1);
        } else {
            CP_WAIT(0);
        }
        __syncthreads();

        // ---- compute on buf
        const uint32_t aBase = sb + Aoff[buf];
        const uint32_t bBase = sb + Boff[buf];
        #pragma unroll
        for (int kf2 = 0; kf2 < 2; ++kf2) {
            const int kf = kf2 * 16;
            uint32_t a[2][4];
            #pragma unroll
            for (int mf = 0; mf < 2; ++mf) {
                uint32_t ad = aBase +
                    ((wm * 32 + mf * 16 + (lane & 15)) * APAD + kf + ((lane >> 4) << 3)) * 2;
                ldm_x4(a[mf], ad);
            }
            #pragma unroll
            for (int nf2 = 0; nf2 < 6; ++nf2) {
                uint32_t bb[4];
                uint32_t bd = bBase +
                    ((kf + (lane & 15)) * BPAD + wn * 96 + nf2 * 16 + ((lane >> 4) << 3)) * 2;
                ldm_x4t(bb, bd);
                mma16816(acc[0][nf2 * 2 + 0], a[0], bb[0], bb[1]);
                mma16816(acc[0][nf2 * 2 + 1], a[0], bb[2], bb[3]);
                mma16816(acc[1][nf2 * 2 + 0], a[1], bb[0], bb[1]);
                mma16816(acc[1][nf2 * 2 + 1], a[1], bb[2], bb[3]);
            }
        }

        if (j < 23) stsA(buf ^ 1, nxt); // STS after compute; other buffer is free
        __syncthreads();
    }

    // ---- epilogue: + bias, fp32 store
    float* dst = img ? g_emby : g_embx;
    const int qid = lane >> 2, tc = lane & 3;
    #pragma unroll
    for (int mf = 0; mf < 2; ++mf) {
        #pragma unroll
        for (int nf = 0; nf < 12; ++nf) {
            int row = m0 + wm * 32 + mf * 16 + qid;
            int col = wn * 96 + nf * 8 + tc * 2;
            float2 bv = *(const float2*)(bias + col);
            float2 o0 = {acc[mf][nf][0] + bv.x, acc[mf][nf][1] + bv.y};
            float2 o1 = {acc[mf][nf][2] + bv.x, acc[mf][nf][3] + bv.y};
            *(float2*)(dst + (size_t)row * HID + col) = o0;
            *(float2*)(dst + (size_t)(row + 8) * HID + col) = o1;
        }
    }
}

// ---------------------------------------------------------- row softmax (y)
__global__ void k_softmax_y() {
    const int row = blockIdx.x;
    float* v = g_emby + (size_t)row * HID;
    const int tid = threadIdx.x;
    float a0 = v[tid], a1 = v[tid + 128], a2 = v[tid + 256];

    __shared__ float red[4];
    float mx = fmaxf(a0, fmaxf(a1, a2));
    #pragma unroll
    for (int o = 16; o; o >>= 1) mx = fmaxf(mx, __shfl_xor_sync(0xffffffffu, mx, o));
    if ((tid & 31) == 0) red[tid >> 5] = mx;
    __syncthreads();
    mx = fmaxf(fmaxf(red[0], red[1]), fmaxf(red[2], red[3]));

    float e0 = __expf(a0 - mx), e1 = __expf(a1 - mx), e2 = __expf(a2 - mx);
    float s = e0 + e1 + e2;
    #pragma unroll
    for (int o = 16; o; o >>= 1) s += __shfl_xor_sync(0xffffffffu, s, o);
    __shared__ float red2[4];
    if ((tid & 31) == 0) red2[tid >> 5] = s;
    __syncthreads();
    s = red2[0] + red2[1] + red2[2] + red2[3];

    float inv = 1.0f / s;
    v[tid] = e0 * inv; v[tid + 128] = e1 * inv; v[tid + 256] = e2 * inv;
}

// -------------------------------------------------------------- row lse (x)
__global__ void k_lse_x() {
    const int row = blockIdx.x;
    const float* v = g_embx + (size_t)row * HID;
    const int tid = threadIdx.x;
    float a0 = v[tid], a1 = v[tid + 128], a2 = v[tid + 256];

    __shared__ float red[4];
    float mx = fmaxf(a0, fmaxf(a1, a2));
    #pragma unroll
    for (int o = 16; o; o >>= 1) mx = fmaxf(mx, __shfl_xor_sync(0xffffffffu, mx, o));
    if ((tid & 31) == 0) red[tid >> 5] = mx;
    __syncthreads();
    mx = fmaxf(fmaxf(red[0], red[1]), fmaxf(red[2], red[3]));

    float s = __expf(a0 - mx) + __expf(a1 - mx) + __expf(a2 - mx);
    #pragma unroll
    for (int o = 16; o; o >>= 1) s += __shfl_xor_sync(0xffffffffu, s, o);
    __shared__ float red2[4];
    if ((tid & 31) == 0) red2[tid >> 5] = s;
    __syncthreads();
    if (tid == 0) {
        s = red2[0] + red2[1] + red2[2] + red2[3];
        g_lse[row] = mx + __logf(s);
    }
}

// ----------------------------------------------------- L[b] = sum_p lse[b,p]
__global__ void k_reduceL() {
    const int b = blockIdx.x;
    const int tid = threadIdx.x;
    float v = (tid < NP) ? g_lse[b * NP + tid] : 0.0f;
    #pragma unroll
    for (int o = 16; o; o >>= 1) v += __shfl_xor_sync(0xffffffffu, v, o);
    __shared__ float red[8];
    if ((tid & 31) == 0) red[tid >> 5] = v;
    __syncthreads();
    if (tid == 0) {
        float s = 0.0f;
        #pragma unroll
        for (int w = 0; w < 8; ++w) s += red[w];
        g_L[b] = s;
    }
}

// ------------------- S partials: one block = one 128-wide k slice (fp32)
__global__ void __launch_bounds__(256) k_sgemm() {
    extern __shared__ float sh[];           // Xs[64][132] | Qs[64][132]
    float* Xs = sh;
    float* Qs = sh + 64 * 132;
    const int tid = threadIdx.x;

    const uint4* Xu = (const uint4*)g_embx;
    const uint4* Qu = (const uint4*)g_emby;
    #pragma unroll
    for (int it = 0; it < 8; ++it) {
        int u = tid + it * 256;             // 2048 uint4 per array
        int row = u >> 5, un = u & 31;
        *(uint4*)&Xs[row * 132 + un * 4] = Xu[(size_t)row * 18816 + blockIdx.x * 32 + un];
        *(uint4*)&Qs[row * 132 + un * 4] = Qu[(size_t)row * 18816 + blockIdx.x * 32 + un];
    }
    __syncthreads();

    const int i0 = (tid >> 4) << 2, j0 = (tid & 15) << 2;
    float acc[4][4] = {};
    #pragma unroll 2
    for (int k4 = 0; k4 < 32; ++k4) {
        float4 a[4], q[4];
        #pragma unroll
        for (int r = 0; r < 4; ++r) {
            a[r] = *(const float4*)&Xs[(i0 + r) * 132 + k4 * 4];
            q[r] = *(const float4*)&Qs[(j0 + r) * 132 + k4 * 4];
        }
        #pragma unroll
        for (int r = 0; r < 4; ++r)
            #pragma unroll
            for (int c = 0; c < 4; ++c)
                acc[r][c] += a[r].x * q[c].x + a[r].y * q[c].y
                           + a[r].z * q[c].z + a[r].w * q[c].w;
    }
    float* dst = g_Spart + (size_t)blockIdx.x * 4096;
    #pragma unroll
    for (int r = 0; r < 4; ++r)
        #pragma unroll
        for (int c = 0; c < 4; ++c)
            dst[(i0 + r) * 64 + j0 + c] = acc[r][c];
}

__global__ void k_sreduce() {
    int idx = blockIdx.x * 256 + threadIdx.x;   // 4096
    float s = 0.0f;
    #pragma unroll 4
    for (int b = 0; b < NKB; ++b) s += g_Spart[(size_t)b * 4096 + idx];
    g_S[idx] = s;
}

// ------------------------------------------------------------- final scalar
__global__ void k_final(float* __restrict__ out) {
    const int tid = threadIdx.x;
    float tot = 0.0f, diag = 0.0f;
    for (int idx = tid; idx < 4096; idx += 256) {
        int i = idx >> 6, j = idx & 63;
        float ce = (g_L[i] - g_S[idx]) * (1.0f / 196.0f);
        tot += ce;
        if (i == j) diag += ce;
    }
    #pragma unroll
    for (int o = 16; o; o >>= 1) {
        tot  += __shfl_xor_sync(0xffffffffu, tot,  o);
        diag += __shfl_xor_sync(0xffffffffu, diag, o);
    }
    __shared__ float rt[8], rd[8];
    if ((tid & 31) == 0) { rt[tid >> 5] = tot; rd[tid >> 5] = diag; }
    __syncthreads();
    if (tid == 0) {
        float T = 0.0f, D = 0.0f;
        #pragma unroll
        for (int w = 0; w < 8; ++w) { T += rt[w]; D += rd[w]; }
        out[0] = (D / 64.0f) / ((T - D) / 4032.0f);
    }
}

// ---------------------------------------------------------------------------
extern "C" void kernel_launch(void* const* d_in, const int* in_sizes, int n_in,
                              void* d_out, int out_size) {
    const float* x  = (const float*)d_in[0];
    const float* y  = (const float*)d_in[1];
    const float* Wc = (const float*)d_in[2];
    const float* b  = (const float*)d_in[3];
    float* out = (float*)d_out;

    cudaFuncSetAttribute(k_gemm, cudaFuncAttributeMaxDynamicSharedMemorySize, SM_GEMM);
    cudaFuncSetAttribute(k_sgemm, cudaFuncAttributeMaxDynamicSharedMemorySize,
                         2 * 64 * 132 * (int)sizeof(float));

    k_prep_w<<<(KDIM * HID + 255) / 256, 256>>>(Wc);
    k_gemm<<<dim3(196, 2), 256, SM_GEMM>>>(x, y, b);
    k_softmax_y<<<MROWS, 128>>>();
    k_lse_x<<<MROWS, 128>>>();
    k_reduceL<<<BSZ, 256>>>();
    k_sgemm<<<NKB, 256, 2 * 64 * 132 * (int)sizeof(float)>>>();
    k_sreduce<<<16, 256>>>();
    k_final<<<1, 256>>>(out);
}

// round 7
// speedup vs baseline: 5.4710x; 1.4120x over previous
#include <cuda_runtime.h>
#include <cuda_bf16.h>
#include <math.h>
#include <stdint.h>

// ---------------------------------------------------------------------------
// PairContrastiveLoss via mma.sync (HMMA bf16), fused softmax/lse epilogue.
//   emb = im2col(x|y) @ W^T + b   (bf16 inputs, fp32 accum, fused im2col)
//   CE[i,j] = (L[i] - S[i,j]) / 196,  S = Xp_raw @ q^T, L[i] = sum_p lse
//   out = (trace/B) / ((sum-trace)/(B^2-B))
// ---------------------------------------------------------------------------

#define BSZ   64
#define NP    196
#define HID   384
#define KDIM  768
#define MROWS 12544
#define KTOT  75264
#define SK    256          // k-chunk for S gemm
#define NKB   294          // KTOT / SK

__device__ __nv_bfloat16 g_Wt[KDIM * HID];                  // [k][n] bf16
__device__ __nv_bfloat16 g_Xb[(size_t)MROWS * HID];         // raw x logits bf16
__device__ __nv_bfloat16 g_Qb[(size_t)MROWS * HID];         // q = softmax(y) bf16
__device__ float g_lse[MROWS];
__device__ float g_L[BSZ];
__device__ float g_Spart[NKB * 4096];
__device__ float g_S[4096];

// ------------------------------------------------------------- PTX helpers
__device__ __forceinline__ uint32_t smem_u32(const void* p) {
    uint32_t a;
    asm("{ .reg .u64 t; cvta.to.shared.u64 t, %1; cvt.u32.u64 %0, t; }"
        : "=r"(a) : "l"(p));
    return a;
}
__device__ __forceinline__ void cp_async16(uint32_t dst, const void* src) {
    asm volatile("cp.async.cg.shared.global [%0], [%1], 16;" :: "r"(dst), "l"(src));
}
#define CP_COMMIT() asm volatile("cp.async.commit_group;" ::: "memory")
#define CP_WAIT(n)  asm volatile("cp.async.wait_group %0;" :: "n"(n) : "memory")

__device__ __forceinline__ void ldm_x4(uint32_t* r, uint32_t addr) {
    asm volatile("ldmatrix.sync.aligned.m8n8.x4.shared.b16 {%0,%1,%2,%3}, [%4];"
        : "=r"(r[0]), "=r"(r[1]), "=r"(r[2]), "=r"(r[3]) : "r"(addr));
}
__device__ __forceinline__ void ldm_x4t(uint32_t* r, uint32_t addr) {
    asm volatile("ldmatrix.sync.aligned.m8n8.x4.trans.shared.b16 {%0,%1,%2,%3}, [%4];"
        : "=r"(r[0]), "=r"(r[1]), "=r"(r[2]), "=r"(r[3]) : "r"(addr));
}
__device__ __forceinline__ void mma16816(float* d, const uint32_t* a,
                                         uint32_t b0, uint32_t b1) {
    asm volatile(
        "mma.sync.aligned.m16n8k16.row.col.f32.bf16.bf16.f32 "
        "{%0,%1,%2,%3}, {%4,%5,%6,%7}, {%8,%9}, {%0,%1,%2,%3};"
        : "+f"(d[0]), "+f"(d[1]), "+f"(d[2]), "+f"(d[3])
        : "r"(a[0]), "r"(a[1]), "r"(a[2]), "r"(a[3]), "r"(b0), "r"(b1));
}

// ------------------------------------------------------------------ prep W
__global__ void k_prep_w(const float* __restrict__ Wc) {
    int idx = blockIdx.x * 256 + threadIdx.x;
    if (idx < KDIM * HID) {
        int k = idx / HID, n = idx - k * HID;
        g_Wt[idx] = __float2bfloat16_rn(Wc[n * KDIM + k]);
    }
}

// ------------------------------------------------ HMMA patch-embed GEMM
// CTA: BM=64 x BN=384 (full N), BK=32, 24 k-iters, 8 warps (2m x 4n).
// Epilogue: bias + full-row softmax(y)->q bf16 / raw bf16 + lse (x).
#define APAD   40
#define BPAD   392
#define A_ST   (64 * APAD * 2)
#define B_ST   (32 * BPAD * 2)
#define SM_A0  0
#define SM_A1  A_ST
#define SM_B0  (2 * A_ST)
#define SM_B1  (2 * A_ST + B_ST)
#define SM_GEMM (2 * A_ST + 2 * B_ST)

__global__ void __launch_bounds__(256) k_gemm(
        const float* __restrict__ x, const float* __restrict__ y,
        const float* __restrict__ bias) {
    extern __shared__ char smem[];
    const uint32_t sb = smem_u32(smem);
    const int tid = threadIdx.x;
    const int lane = tid & 31;
    const int wid = tid >> 5;
    const int wm = wid >> 2;            // 0..1
    const int wn = wid & 3;             // 0..3
    const int m0 = blockIdx.x * 64;
    const int img = blockIdx.y;
    const float* im = img ? y : x;

    const int r_a = tid >> 3;
    const int s_a = tid & 7;
    const int srr  = s_a >> 2;
    const int col4 = (s_a & 3) * 4;
    int base_r[2];
    #pragma unroll
    for (int h = 0; h < 2; ++h) {
        int m = m0 + r_a + h * 32;
        int b = m / NP, p = m - b * NP;
        int ph = p / 14, pw = p - ph * 14;
        base_r[h] = (b * 3 * 224 + ph * 16) * 224 + pw * 16 + col4;
    }
    const uint32_t a_dst_e = r_a * APAD + srr * 16 + (s_a & 3) * 4;

    const uint32_t Aoff[2] = {SM_A0, SM_A1};
    const uint32_t Boff[2] = {SM_B0, SM_B1};

    float acc[2][12][4] = {};

    auto issueB = [&](int j, int buf) {
        #pragma unroll
        for (int it = 0; it < 6; ++it) {
            int idx = tid + it * 256;
            int row = idx / 48, seg = idx - row * 48;
            cp_async16(sb + Boff[buf] + row * (BPAD * 2) + seg * 16,
                       g_Wt + (size_t)(j * 32 + row) * HID + seg * 8);
        }
        CP_COMMIT();
    };
    auto ldgA = [&](int j, float4* av) {
        const int c = j >> 3, r0 = (j & 7) * 2;
        const int off = c * 50176 + (r0 + srr) * 224;
        av[0] = *(const float4*)(im + base_r[0] + off);
        av[1] = *(const float4*)(im + base_r[1] + off);
    };
    auto stsA = [&](int buf, const float4* av) {
        #pragma unroll
        for (int h = 0; h < 2; ++h) {
            __nv_bfloat162 p0 = __floats2bfloat162_rn(av[h].x, av[h].y);
            __nv_bfloat162 p1 = __floats2bfloat162_rn(av[h].z, av[h].w);
            char* d = smem + Aoff[buf] + (a_dst_e + h * 32 * APAD) * 2;
            *(uint32_t*)d       = *(uint32_t*)&p0;
            *(uint32_t*)(d + 4) = *(uint32_t*)&p1;
        }
    };

    {
        float4 av[2];
        ldgA(0, av);
        stsA(0, av);
        issueB(0, 0);
    }

    float4 nxt[2];
    for (int j = 0; j < 24; ++j) {
        const int buf = j & 1;
        if (j < 23) {
            ldgA(j + 1, nxt);
            issueB(j + 1, buf ^ 1);
            CP_WAIT(1);
        } else {
            CP_WAIT(0);
        }
        __syncthreads();

        const uint32_t aBase = sb + Aoff[buf];
        const uint32_t bBase = sb + Boff[buf];
        #pragma unroll
        for (int kf2 = 0; kf2 < 2; ++kf2) {
            const int kf = kf2 * 16;
            uint32_t a[2][4];
            #pragma unroll
            for (int mf = 0; mf < 2; ++mf) {
                uint32_t ad = aBase +
                    ((wm * 32 + mf * 16 + (lane & 15)) * APAD + kf + ((lane >> 4) << 3)) * 2;
                ldm_x4(a[mf], ad);
            }
            #pragma unroll
            for (int nf2 = 0; nf2 < 6; ++nf2) {
                uint32_t bb[4];
                uint32_t bd = bBase +
                    ((kf + (lane & 15)) * BPAD + wn * 96 + nf2 * 16 + ((lane >> 4) << 3)) * 2;
                ldm_x4t(bb, bd);
                mma16816(acc[0][nf2 * 2 + 0], a[0], bb[0], bb[1]);
                mma16816(acc[0][nf2 * 2 + 1], a[0], bb[2], bb[3]);
                mma16816(acc[1][nf2 * 2 + 0], a[1], bb[0], bb[1]);
                mma16816(acc[1][nf2 * 2 + 1], a[1], bb[2], bb[3]);
            }
        }

        if (j < 23) stsA(buf ^ 1, nxt);
        __syncthreads();
    }

    // ================= fused epilogue: bias + softmax/lse =================
    const int qid = lane >> 2, tc = lane & 3;

    // add bias into accumulators
    #pragma unroll
    for (int nf = 0; nf < 12; ++nf) {
        float2 bv = *(const float2*)(bias + wn * 96 + nf * 8 + tc * 2);
        #pragma unroll
        for (int mf = 0; mf < 2; ++mf) {
            acc[mf][nf][0] += bv.x; acc[mf][nf][1] += bv.y;
            acc[mf][nf][2] += bv.x; acc[mf][nf][3] += bv.y;
        }
    }

    float* sMax = (float*)smem;              // [64][4]
    float* sSum = (float*)(smem + 1024);     // [64][4]

    // row-local max (rows: wm*32 + mf*16 + h*8 + qid)
    float mx[2][2];
    #pragma unroll
    for (int mf = 0; mf < 2; ++mf)
        #pragma unroll
        for (int h = 0; h < 2; ++h) {
            float m = -1e30f;
            #pragma unroll
            for (int nf = 0; nf < 12; ++nf)
                m = fmaxf(m, fmaxf(acc[mf][nf][h * 2], acc[mf][nf][h * 2 + 1]));
            m = fmaxf(m, __shfl_xor_sync(0xffffffffu, m, 1));
            m = fmaxf(m, __shfl_xor_sync(0xffffffffu, m, 2));
            mx[mf][h] = m;
        }
    if (tc == 0) {
        #pragma unroll
        for (int mf = 0; mf < 2; ++mf)
            #pragma unroll
            for (int h = 0; h < 2; ++h)
                sMax[(wm * 32 + mf * 16 + h * 8 + qid) * 4 + wn] = mx[mf][h];
    }
    __syncthreads();
    float gmx[2][2];
    #pragma unroll
    for (int mf = 0; mf < 2; ++mf)
        #pragma unroll
        for (int h = 0; h < 2; ++h) {
            const float* r = &sMax[(wm * 32 + mf * 16 + h * 8 + qid) * 4];
            gmx[mf][h] = fmaxf(fmaxf(r[0], r[1]), fmaxf(r[2], r[3]));
        }
    // exp-sums
    float sm[2][2];
    #pragma unroll
    for (int mf = 0; mf < 2; ++mf)
        #pragma unroll
        for (int h = 0; h < 2; ++h) {
            float s = 0.0f;
            #pragma unroll
            for (int nf = 0; nf < 12; ++nf)
                s += __expf(acc[mf][nf][h * 2] - gmx[mf][h])
                   + __expf(acc[mf][nf][h * 2 + 1] - gmx[mf][h]);
            s += __shfl_xor_sync(0xffffffffu, s, 1);
            s += __shfl_xor_sync(0xffffffffu, s, 2);
            sm[mf][h] = s;
        }
    __syncthreads();        // sMax no longer needed before sSum writes overlap? distinct buffer; keep order
    if (tc == 0) {
        #pragma unroll
        for (int mf = 0; mf < 2; ++mf)
            #pragma unroll
            for (int h = 0; h < 2; ++h)
                sSum[(wm * 32 + mf * 16 + h * 8 + qid) * 4 + wn] = sm[mf][h];
    }
    __syncthreads();

    __nv_bfloat16* dst = img ? g_Qb : g_Xb;
    #pragma unroll
    for (int mf = 0; mf < 2; ++mf) {
        #pragma unroll
        for (int h = 0; h < 2; ++h) {
            const int mloc = wm * 32 + mf * 16 + h * 8 + qid;
            const int row = m0 + mloc;
            const float* r = &sSum[mloc * 4];
            const float den = r[0] + r[1] + r[2] + r[3];
            if (img == 0) {
                if (wn == 0 && tc == 0) g_lse[row] = gmx[mf][h] + __logf(den);
                #pragma unroll
                for (int nf = 0; nf < 12; ++nf) {
                    __nv_bfloat162 p = __floats2bfloat162_rn(
                        acc[mf][nf][h * 2], acc[mf][nf][h * 2 + 1]);
                    *(uint32_t*)(dst + (size_t)row * HID + wn * 96 + nf * 8 + tc * 2)
                        = *(uint32_t*)&p;
                }
            } else {
                const float inv = 1.0f / den;
                const float g = gmx[mf][h];
                #pragma unroll
                for (int nf = 0; nf < 12; ++nf) {
                    __nv_bfloat162 p = __floats2bfloat162_rn(
                        __expf(acc[mf][nf][h * 2] - g) * inv,
                        __expf(acc[mf][nf][h * 2 + 1] - g) * inv);
                    *(uint32_t*)(dst + (size_t)row * HID + wn * 96 + nf * 8 + tc * 2)
                        = *(uint32_t*)&p;
                }
            }
        }
    }
}

// ----------------------------------------------------- L[b] = sum_p lse[b,p]
__global__ void k_reduceL() {
    const int b = blockIdx.x;
    const int tid = threadIdx.x;
    float v = (tid < NP) ? g_lse[b * NP + tid] : 0.0f;
    #pragma unroll
    for (int o = 16; o; o >>= 1) v += __shfl_xor_sync(0xffffffffu, v, o);
    __shared__ float red[8];
    if ((tid & 31) == 0) red[tid >> 5] = v;
    __syncthreads();
    if (tid == 0) {
        float s = 0.0f;
        #pragma unroll
        for (int w = 0; w < 8; ++w) s += red[w];
        g_L[b] = s;
    }
}

// ---------------- S partials via HMMA: block = one 256-wide k slice
// X[64][SK] bf16, Q[64][SK] bf16 in smem; 8 warps = 4m x 2n; warp: m16 x n32.
#define SPAD 264                        // SK + 8 elems
__global__ void __launch_bounds__(256) k_sgemm() {
    extern __shared__ char sh[];
    __nv_bfloat16* Xs = (__nv_bfloat16*)sh;
    __nv_bfloat16* Qs = (__nv_bfloat16*)(sh + 64 * SPAD * 2);
    const uint32_t xb = smem_u32(Xs), qb = smem_u32(Qs);
    const int tid = threadIdx.x;
    const int lane = tid & 31;
    const int wid = tid >> 5;
    const int wm2 = wid >> 1;           // 0..3
    const int wn2 = wid & 1;            // 0..1

    const uint4* Xu = (const uint4*)g_Xb;
    const uint4* Qu = (const uint4*)g_Qb;
    const int kb32 = blockIdx.x * 32;   // uint4 offset in row
    #pragma unroll
    for (int it = 0; it < 8; ++it) {
        int u = tid + it * 256;
        int row = u >> 5, un = u & 31;
        *(uint4*)(Xs + row * SPAD + un * 8) = Xu[(size_t)row * 9408 + kb32 + un];
        *(uint4*)(Qs + row * SPAD + un * 8) = Qu[(size_t)row * 9408 + kb32 + un];
    }
    __syncthreads();

    float acc[4][4] = {};
    #pragma unroll 4
    for (int ks = 0; ks < 16; ++ks) {
        const uint32_t koff = (ks * 16 + ((lane >> 4) << 3)) * 2;
        uint32_t a[4], b0[4], b1[4];
        ldm_x4(a,  xb + (wm2 * 16 + (lane & 15)) * (SPAD * 2) + koff);
        ldm_x4(b0, qb + (wn2 * 32 + (lane & 15)) * (SPAD * 2) + koff);
        ldm_x4(b1, qb + (wn2 * 32 + 16 + (lane & 15)) * (SPAD * 2) + koff);
        mma16816(acc[0], a, b0[0], b0[1]);
        mma16816(acc[1], a, b0[2], b0[3]);
        mma16816(acc[2], a, b1[0], b1[1]);
        mma16816(acc[3], a, b1[2], b1[3]);
    }

    float* dst = g_Spart + (size_t)blockIdx.x * 4096;
    const int qid = lane >> 2, tc = lane & 3;
    #pragma unroll
    for (int t = 0; t < 4; ++t) {
        int i0 = wm2 * 16 + qid;
        int j  = wn2 * 32 + t * 8 + tc * 2;
        *(float2*)(dst + i0 * 64 + j)       = make_float2(acc[t][0], acc[t][1]);
        *(float2*)(dst + (i0 + 8) * 64 + j) = make_float2(acc[t][2], acc[t][3]);
    }
}

__global__ void k_sreduce() {
    int idx = blockIdx.x * 256 + threadIdx.x;   // 4096
    float s = 0.0f;
    #pragma unroll 2
    for (int b = 0; b < NKB; ++b) s += g_Spart[(size_t)b * 4096 + idx];
    g_S[idx] = s;
}

// ------------------------------------------------------------- final scalar
__global__ void k_final(float* __restrict__ out) {
    const int tid = threadIdx.x;
    float tot = 0.0f, diag = 0.0f;
    for (int idx = tid; idx < 4096; idx += 256) {
        int i = idx >> 6, j = idx & 63;
        float ce = (g_L[i] - g_S[idx]) * (1.0f / 196.0f);
        tot += ce;
        if (i == j) diag += ce;
    }
    #pragma unroll
    for (int o = 16; o; o >>= 1) {
        tot  += __shfl_xor_sync(0xffffffffu, tot,  o);
        diag += __shfl_xor_sync(0xffffffffu, diag, o);
    }
    __shared__ float rt[8], rd[8];
    if ((tid & 31) == 0) { rt[tid >> 5] = tot; rd[tid >> 5] = diag; }
    __syncthreads();
    if (tid == 0) {
        float T = 0.0f, D = 0.0f;
        #pragma unroll
        for (int w = 0; w < 8; ++w) { T += rt[w]; D += rd[w]; }
        out[0] = (D / 64.0f) / ((T - D) / 4032.0f);
    }
}

// ---------------------------------------------------------------------------
extern "C" void kernel_launch(void* const* d_in, const int* in_sizes, int n_in,
                              void* d_out, int out_size) {
    const float* x  = (const float*)d_in[0];
    const float* y  = (const float*)d_in[1];
    const float* Wc = (const float*)d_in[2];
    const float* b  = (const float*)d_in[3];
    float* out = (float*)d_out;

    const int SM_S = 2 * 64 * SPAD * 2;   // 67584 B

    cudaFuncSetAttribute(k_gemm, cudaFuncAttributeMaxDynamicSharedMemorySize, SM_GEMM);
    cudaFuncSetAttribute(k_sgemm, cudaFuncAttributeMaxDynamicSharedMemorySize, SM_S);

    k_prep_w<<<(KDIM * HID + 255) / 256, 256>>>(Wc);
    k_gemm<<<dim3(196, 2), 256, SM_GEMM>>>(x, y, b);
    k_reduceL<<<BSZ, 256>>>();
    k_sgemm<<<NKB, 256, SM_S>>>();
    k_sreduce<<<16, 256>>>();
    k_final<<<1, 256>>>(out);
}